// round 1
// baseline (speedup 1.0000x reference)
#include <cuda_runtime.h>
#include <cuda_bf16.h>

// ShiftConv: group-wise spatial shift (4 groups x 128 ch, roll +-1 on H or W)
// -> 1x1 conv (GEMM M=50176, N=512, K=512) -> folded BN -> ReLU.
//
// Round 1: fp32 register-blocked SGEMM baseline with fused shift-gather and
// epilogue. 128x128x16 tiles, 256 threads, 8x8 microtiles.

#define HDIM 28
#define HW   784          // 28*28
#define CCH  512          // C == Cout == K
#define EPSV 1e-5f

__global__ __launch_bounds__(256, 2)
void shiftconv_kernel(const float* __restrict__ x,
                      const float* __restrict__ Wm,
                      const float* __restrict__ gamma,
                      const float* __restrict__ beta,
                      const float* __restrict__ rmean,
                      const float* __restrict__ rvar,
                      float* __restrict__ out)
{
    __shared__ float As[16][128];   // [k][p]
    __shared__ float Bs[16][132];   // [k][o], padded row to soften store conflicts
    __shared__ int   soffs[4][128]; // per-group shifted source offset (b*C*HW + hs*28 + ws)

    const int tid    = threadIdx.x;
    const int pblock = blockIdx.x * 128;  // position tile base (0..50048)
    const int oblock = blockIdx.y * 128;  // output-channel tile base (0..384)

    // Precompute shifted spatial source offsets for this position tile, all 4 groups.
    // roll(a, s)[i] = a[(i - s) mod n]  =>  shift -1 reads index (i+1)%n, +1 reads (i-1)%n.
    for (int idx = tid; idx < 512; idx += 256) {
        int g  = idx >> 7;
        int p  = idx & 127;
        int pg = pblock + p;
        int b  = pg / HW;
        int hw = pg - b * HW;
        int h  = hw / HDIM;
        int w  = hw - h * HDIM;
        int hs = h, ws = w;
        if      (g == 0) hs = (h + 1) % HDIM;          // roll -1 along H
        else if (g == 1) hs = (h + HDIM - 1) % HDIM;   // roll +1 along H
        else if (g == 2) ws = (w + 1) % HDIM;          // roll -1 along W
        else             ws = (w + HDIM - 1) % HDIM;   // roll +1 along W
        soffs[g][p] = b * (CCH * HW) + hs * HDIM + ws;
    }
    __syncthreads();

    float acc[8][8];
    #pragma unroll
    for (int j = 0; j < 8; j++)
        #pragma unroll
        for (int i = 0; i < 8; i++) acc[j][i] = 0.0f;

    const int pfrag = (tid & 15) * 8;   // position fragment within tile
    const int ofrag = (tid >> 4) * 8;   // output-channel fragment within tile

    for (int kc = 0; kc < CCH; kc += 16) {
        const int g = kc >> 7;   // 16-wide k-chunk never straddles a 128-ch group

        // Load A tile: 128 positions x 16 channels (gathered with the group shift).
        // Consecutive lanes -> consecutive positions -> (mostly) contiguous gmem.
        #pragma unroll
        for (int i = 0; i < 8; i++) {
            int linear = tid + i * 256;
            int k = linear >> 7;
            int p = linear & 127;
            As[k][p] = __ldg(&x[(kc + k) * HW + soffs[g][p]]);
        }

        // Load B tile: 128 outputs x 16 k, float4 along k (W is [o][c] row-major).
        #pragma unroll
        for (int i = 0; i < 2; i++) {
            int l4 = tid + i * 256;
            int o  = l4 >> 2;
            int kq = (l4 & 3) * 4;
            float4 v = *reinterpret_cast<const float4*>(
                &Wm[(oblock + o) * CCH + kc + kq]);
            Bs[kq + 0][o] = v.x;
            Bs[kq + 1][o] = v.y;
            Bs[kq + 2][o] = v.z;
            Bs[kq + 3][o] = v.w;
        }
        __syncthreads();

        #pragma unroll
        for (int kk = 0; kk < 16; kk++) {
            float a[8], bb[8];
            *(float4*)&a[0]  = *(const float4*)&As[kk][pfrag];
            *(float4*)&a[4]  = *(const float4*)&As[kk][pfrag + 4];
            *(float4*)&bb[0] = *(const float4*)&Bs[kk][ofrag];
            *(float4*)&bb[4] = *(const float4*)&Bs[kk][ofrag + 4];
            #pragma unroll
            for (int j = 0; j < 8; j++)
                #pragma unroll
                for (int i = 0; i < 8; i++)
                    acc[j][i] = fmaf(bb[j], a[i], acc[j][i]);
        }
        __syncthreads();
    }

    // Epilogue: folded BN (scale/shift from running stats) + ReLU, float4 stores.
    // 784 % 8 == 0 and pfrag is 8-aligned -> an 8-wide p fragment never crosses
    // a batch boundary, so b/hw are fragment constants and stores are 16B-aligned.
    const int p0  = pblock + pfrag;
    const int b   = p0 / HW;
    const int hw0 = p0 - b * HW;
    #pragma unroll
    for (int j = 0; j < 8; j++) {
        int   o  = oblock + ofrag + j;
        float sc = gamma[o] * rsqrtf(rvar[o] + EPSV);
        float sh = beta[o] - rmean[o] * sc;
        float* po = out + ((size_t)(b * CCH + o)) * HW + hw0;
        float4 v0, v1;
        v0.x = fmaxf(fmaf(acc[j][0], sc, sh), 0.0f);
        v0.y = fmaxf(fmaf(acc[j][1], sc, sh), 0.0f);
        v0.z = fmaxf(fmaf(acc[j][2], sc, sh), 0.0f);
        v0.w = fmaxf(fmaf(acc[j][3], sc, sh), 0.0f);
        v1.x = fmaxf(fmaf(acc[j][4], sc, sh), 0.0f);
        v1.y = fmaxf(fmaf(acc[j][5], sc, sh), 0.0f);
        v1.z = fmaxf(fmaf(acc[j][6], sc, sh), 0.0f);
        v1.w = fmaxf(fmaf(acc[j][7], sc, sh), 0.0f);
        *(float4*)&po[0] = v0;
        *(float4*)&po[4] = v1;
    }
}

extern "C" void kernel_launch(void* const* d_in, const int* in_sizes, int n_in,
                              void* d_out, int out_size)
{
    const float* x     = (const float*)d_in[0];
    const float* Wm    = (const float*)d_in[1];
    const float* gamma = (const float*)d_in[2];
    const float* beta  = (const float*)d_in[3];
    const float* rmean = (const float*)d_in[4];
    const float* rvar  = (const float*)d_in[5];
    float* out = (float*)d_out;

    // M = 50176 = 392 * 128 exactly; N = 512 = 4 * 128 exactly -> no tails.
    dim3 grid(392, 4);
    shiftconv_kernel<<<grid, 256>>>(x, Wm, gamma, beta, rmean, rvar, out);
}

// round 2
// speedup vs baseline: 1.2450x; 1.2450x over previous
#include <cuda_runtime.h>
#include <cuda_bf16.h>
#include <cstdint>

// ShiftConv: group-wise spatial shift (4 groups x 128 ch, roll +-1 on H or W)
// -> 1x1 conv (GEMM M=50176, N=512, K=512) -> folded BN -> ReLU.
//
// Round 2: bf16 split-K tensor-core GEMM (mma.sync m16n8k16, hi/lo 2-term
// split for fp32-grade accuracy). 128x128 block tile, K-step 32, 8 warps,
// each warp 32x64 via 2x8 HMMA tiles x 3 split terms.

#define HDIM 28
#define HW   784
#define CCH  512
#define EPSV 1e-5f

#define MMA_BF16(C, A, B) \
  asm volatile("mma.sync.aligned.m16n8k16.row.col.f32.bf16.bf16.f32 " \
    "{%0,%1,%2,%3}, {%4,%5,%6,%7}, {%8,%9}, {%0,%1,%2,%3};" \
    : "+f"((C)[0]), "+f"((C)[1]), "+f"((C)[2]), "+f"((C)[3]) \
    : "r"((A)[0]), "r"((A)[1]), "r"((A)[2]), "r"((A)[3]), \
      "r"((B)[0]), "r"((B)[1]))

// smem stride for 32-wide k tiles, padded to reduce bank conflicts
#define KST 36

__global__ __launch_bounds__(256, 2)
void shiftconv_kernel(const float* __restrict__ x,
                      const float* __restrict__ Wm,
                      const float* __restrict__ gamma,
                      const float* __restrict__ beta,
                      const float* __restrict__ rmean,
                      const float* __restrict__ rvar,
                      float* __restrict__ out)
{
    __shared__ __nv_bfloat16 Ahi[128][KST], Alo[128][KST];
    __shared__ __nv_bfloat16 Bhi[128][KST], Blo[128][KST];
    __shared__ int   soffs[4][128];
    __shared__ float ssc[128], ssh[128];

    const int tid    = threadIdx.x;
    const int lane   = tid & 31;
    const int wid    = tid >> 5;
    const int wm     = wid & 3;        // warp m index: 4 x 32 rows
    const int wn     = wid >> 2;       // warp n index: 2 x 64 cols
    const int g8     = lane >> 2;      // mma groupID (0..7)
    const int tig2   = (lane & 3) * 2; // mma k/col pair base

    const int pblock = blockIdx.x * 128;
    const int oblock = blockIdx.y * 128;

    // Shifted source offsets for this position tile (all 4 channel groups).
    for (int idx = tid; idx < 512; idx += 256) {
        int gg = idx >> 7;
        int p  = idx & 127;
        int pg = pblock + p;
        int b  = pg / HW;
        int hw = pg - b * HW;
        int h  = hw / HDIM;
        int w  = hw - h * HDIM;
        int hs = h, ws = w;
        if      (gg == 0) hs = (h + 1) % HDIM;
        else if (gg == 1) hs = (h + HDIM - 1) % HDIM;
        else if (gg == 2) ws = (w + 1) % HDIM;
        else              ws = (w + HDIM - 1) % HDIM;
        soffs[gg][p] = b * (CCH * HW) + hs * HDIM + ws;
    }
    // Folded BN scale/shift for this o tile.
    if (tid < 128) {
        int o = oblock + tid;
        float sc = gamma[o] * rsqrtf(rvar[o] + EPSV);
        ssc[tid] = sc;
        ssh[tid] = beta[o] - rmean[o] * sc;
    }
    __syncthreads();

    float acc[2][8][4];
    #pragma unroll
    for (int mt = 0; mt < 2; mt++)
        #pragma unroll
        for (int nt = 0; nt < 8; nt++)
            #pragma unroll
            for (int r = 0; r < 4; r++) acc[mt][nt][r] = 0.0f;

    for (int kc = 0; kc < CCH; kc += 32) {
        const int gg = kc >> 7;   // 32-wide k-chunk stays inside a 128-ch group

        // A tile: 128 positions x 32 channels, gathered with the group shift,
        // split into hi/lo bf16. Consecutive lanes -> consecutive positions.
        #pragma unroll
        for (int i = 0; i < 16; i++) {
            int lin = tid + i * 256;
            int k = lin >> 7;
            int p = lin & 127;
            float v = __ldg(&x[(kc + k) * HW + soffs[gg][p]]);
            __nv_bfloat16 h = __float2bfloat16(v);
            Ahi[p][k] = h;
            Alo[p][k] = __float2bfloat16(v - __bfloat162float(h));
        }
        // B tile: 128 outputs x 32 k, float4 along k, split hi/lo.
        #pragma unroll
        for (int i = 0; i < 4; i++) {
            int l4 = tid + i * 256;
            int o  = l4 >> 3;
            int kq = (l4 & 7) * 4;
            float4 v = *reinterpret_cast<const float4*>(
                &Wm[(oblock + o) * CCH + kc + kq]);
            float vv[4] = {v.x, v.y, v.z, v.w};
            #pragma unroll
            for (int j = 0; j < 4; j++) {
                __nv_bfloat16 h = __float2bfloat16(vv[j]);
                Bhi[o][kq + j] = h;
                Blo[o][kq + j] = __float2bfloat16(vv[j] - __bfloat162float(h));
            }
        }
        __syncthreads();

        #pragma unroll
        for (int kk = 0; kk < 32; kk += 16) {
            uint32_t ah[2][4], al[2][4];
            #pragma unroll
            for (int mt = 0; mt < 2; mt++) {
                int m0 = wm * 32 + mt * 16 + g8;
                const __nv_bfloat16* ph = &Ahi[m0][kk + tig2];
                const __nv_bfloat16* pl = &Alo[m0][kk + tig2];
                ah[mt][0] = *(const uint32_t*)(ph);
                ah[mt][1] = *(const uint32_t*)(ph + 8 * KST);
                ah[mt][2] = *(const uint32_t*)(ph + 8);
                ah[mt][3] = *(const uint32_t*)(ph + 8 * KST + 8);
                al[mt][0] = *(const uint32_t*)(pl);
                al[mt][1] = *(const uint32_t*)(pl + 8 * KST);
                al[mt][2] = *(const uint32_t*)(pl + 8);
                al[mt][3] = *(const uint32_t*)(pl + 8 * KST + 8);
            }
            #pragma unroll
            for (int nt = 0; nt < 8; nt++) {
                uint32_t bh[2], bl[2];
                int n0 = wn * 64 + nt * 8 + g8;
                const __nv_bfloat16* ph = &Bhi[n0][kk + tig2];
                const __nv_bfloat16* pl = &Blo[n0][kk + tig2];
                bh[0] = *(const uint32_t*)(ph);
                bh[1] = *(const uint32_t*)(ph + 8);
                bl[0] = *(const uint32_t*)(pl);
                bl[1] = *(const uint32_t*)(pl + 8);
                #pragma unroll
                for (int mt = 0; mt < 2; mt++) {
                    MMA_BF16(acc[mt][nt], ah[mt], bh);   // hi*hi
                    MMA_BF16(acc[mt][nt], ah[mt], bl);   // hi*lo
                    MMA_BF16(acc[mt][nt], al[mt], bh);   // lo*hi
                }
            }
        }
        __syncthreads();
    }

    // Epilogue: BN + ReLU. acc[mt][nt] covers rows {p0, p0+8}, cols {o0, o0+1}.
    #pragma unroll
    for (int mt = 0; mt < 2; mt++) {
        int p0 = pblock + wm * 32 + mt * 16 + g8;
        int p1 = p0 + 8;
        int b0 = p0 / HW, hw0 = p0 - b0 * HW;
        int b1 = p1 / HW, hw1 = p1 - b1 * HW;
        #pragma unroll
        for (int nt = 0; nt < 8; nt++) {
            int oo  = wn * 64 + nt * 8 + tig2;
            float sc0 = ssc[oo],     sh0 = ssh[oo];
            float sc1 = ssc[oo + 1], sh1 = ssh[oo + 1];
            int o0 = oblock + oo;
            float* q00 = out + ((size_t)(b0 * CCH + o0)) * HW + hw0;
            float* q01 = out + ((size_t)(b0 * CCH + o0 + 1)) * HW + hw0;
            float* q10 = out + ((size_t)(b1 * CCH + o0)) * HW + hw1;
            float* q11 = out + ((size_t)(b1 * CCH + o0 + 1)) * HW + hw1;
            *q00 = fmaxf(fmaf(acc[mt][nt][0], sc0, sh0), 0.0f);
            *q01 = fmaxf(fmaf(acc[mt][nt][1], sc1, sh1), 0.0f);
            *q10 = fmaxf(fmaf(acc[mt][nt][2], sc0, sh0), 0.0f);
            *q11 = fmaxf(fmaf(acc[mt][nt][3], sc1, sh1), 0.0f);
        }
    }
}

extern "C" void kernel_launch(void* const* d_in, const int* in_sizes, int n_in,
                              void* d_out, int out_size)
{
    const float* x     = (const float*)d_in[0];
    const float* Wm    = (const float*)d_in[1];
    const float* gamma = (const float*)d_in[2];
    const float* beta  = (const float*)d_in[3];
    const float* rmean = (const float*)d_in[4];
    const float* rvar  = (const float*)d_in[5];
    float* out = (float*)d_out;

    // M = 50176 = 392 * 128, N = 512 = 4 * 128 -> no tails.
    dim3 grid(392, 4);
    shiftconv_kernel<<<grid, 256>>>(x, Wm, gamma, beta, rmean, rvar, out);
}

// round 4
// speedup vs baseline: 3.6894x; 2.9633x over previous
#include <cuda_runtime.h>
#include <cuda_bf16.h>
#include <cstdint>

// ShiftConv: shift -> 1x1 conv (GEMM M=50176,N=512,K=512) -> BN -> ReLU.
// Round 4: tcgen05 unavailable (harness PTX targets sm_103, not sm_103a).
// Pipelined mma.sync bf16 kernel instead:
//  - prepass splits W and SHIFTED x into bf16 hi/lo device globals (once)
//  - main GEMM: cp.async double-buffered staging, K-step 32, 128x128 tile,
//    3-term split MMAs issued term-major to break accumulator RAW chains.

#define HDIM 28
#define HW   784
#define CCH  512
#define EPSV 1e-5f

#define MMA_BF16(C, A, B) \
  asm volatile("mma.sync.aligned.m16n8k16.row.col.f32.bf16.bf16.f32 " \
    "{%0,%1,%2,%3}, {%4,%5,%6,%7}, {%8,%9}, {%0,%1,%2,%3};" \
    : "+f"((C)[0]), "+f"((C)[1]), "+f"((C)[2]), "+f"((C)[3]) \
    : "r"((A)[0]), "r"((A)[1]), "r"((A)[2]), "r"((A)[3]), \
      "r"((B)[0]), "r"((B)[1]))

#define CP16(dst, src) \
  asm volatile("cp.async.ca.shared.global [%0], [%1], 16;" :: "r"(dst), "l"(src))
#define CPCOMMIT() asm volatile("cp.async.commit_group;" ::: "memory")
#define CPWAIT(n)  asm volatile("cp.async.wait_group %0;" :: "n"(n) : "memory")

// smem row stride for K-step 32 tiles: 32 real + 8 pad bf16 (80B, 16B aligned)
#define KST 40
#define MAT_BYTES (128 * KST * 2)          // 10240
#define AH_OFF 0
#define AL_OFF (1 * MAT_BYTES)
#define BH_OFF (2 * MAT_BYTES)
#define BL_OFF (3 * MAT_BYTES)
#define STAGE_BYTES (4 * MAT_BYTES)        // 40960
#define SMEM_TOTAL (2 * STAGE_BYTES)       // 81920

__device__ __nv_bfloat16 g_Whi[CCH * CCH];
__device__ __nv_bfloat16 g_Wlo[CCH * CCH];
__device__ __nv_bfloat16 g_Ahi[(size_t)50176 * CCH];   // shifted x, [p][c]
__device__ __nv_bfloat16 g_Alo[(size_t)50176 * CCH];

__device__ __forceinline__ uint32_t smem_u32(const void* p) {
    uint32_t a;
    asm("{ .reg .u64 t; cvta.to.shared.u64 t, %1; cvt.u32.u64 %0, t; }"
        : "=r"(a) : "l"(p));
    return a;
}

__global__ void split_w_kernel(const float* __restrict__ Wm) {
    int i = blockIdx.x * 256 + threadIdx.x;
    float v = Wm[i];
    __nv_bfloat16 h = __float2bfloat16(v);
    g_Whi[i] = h;
    g_Wlo[i] = __float2bfloat16(v - __bfloat162float(h));
}

// Gather (shift) + transpose + bf16 split: x[B,C,H,W] -> Ahi/Alo[p][c].
// One block = 64 positions x 64 channels (a 64-ch block never straddles the
// 128-ch shift groups).
__global__ __launch_bounds__(256)
void shift_split_x(const float* __restrict__ x) {
    __shared__ float tile[64][65];
    __shared__ int soff[64];
    const int tid = threadIdx.x;
    const int p0 = blockIdx.x * 64;
    const int c0 = blockIdx.y * 64;
    const int g  = c0 >> 7;

    if (tid < 64) {
        int pg = p0 + tid;
        int b  = pg / HW;
        int hw = pg - b * HW;
        int h  = hw / HDIM;
        int w  = hw - h * HDIM;
        int hs = h, ws = w;
        if      (g == 0) hs = (h + 1) % HDIM;
        else if (g == 1) hs = (h + HDIM - 1) % HDIM;
        else if (g == 2) ws = (w + 1) % HDIM;
        else             ws = (w + HDIM - 1) % HDIM;
        soff[tid] = b * (CCH * HW) + hs * HDIM + ws;
    }
    __syncthreads();
    #pragma unroll
    for (int it = 0; it < 16; it++) {       // read coalesced over p
        int lin = tid + it * 256;
        int c = lin >> 6, p = lin & 63;
        tile[c][p] = x[(size_t)(c0 + c) * HW + soff[p]];
    }
    __syncthreads();
    #pragma unroll
    for (int it = 0; it < 16; it++) {       // write coalesced over c
        int lin = tid + it * 256;
        int p = lin >> 6, c = lin & 63;
        float v = tile[c][p];
        __nv_bfloat16 h = __float2bfloat16(v);
        size_t oi = (size_t)(p0 + p) * CCH + c0 + c;
        g_Ahi[oi] = h;
        g_Alo[oi] = __float2bfloat16(v - __bfloat162float(h));
    }
}

__global__ __launch_bounds__(256, 2)
void shiftconv_gemm(const float* __restrict__ gamma,
                    const float* __restrict__ beta,
                    const float* __restrict__ rmean,
                    const float* __restrict__ rvar,
                    float* __restrict__ out)
{
    extern __shared__ char dsm[];
    __shared__ float ssc[128], ssh[128];

    const int tid  = threadIdx.x;
    const int lane = tid & 31;
    const int wid  = tid >> 5;
    const int wm   = wid & 3;
    const int wn   = wid >> 2;
    const int g8   = lane >> 2;
    const int tig2 = (lane & 3) * 2;

    const int pblock = blockIdx.x * 128;
    const int oblock = blockIdx.y * 128;

    if (tid < 128) {
        int o = oblock + tid;
        float sc = gamma[o] * rsqrtf(rvar[o] + EPSV);
        ssc[tid] = sc;
        ssh[tid] = beta[o] - rmean[o] * sc;
    }

    const uint32_t sdyn = smem_u32(dsm);

    // stage loader: 8 x 16B cp.async per thread (Ahi/Alo/Bhi/Blo, 64B per row)
    auto load_stage = [&](int kc, int buf) {
        uint32_t st = sdyn + buf * STAGE_BYTES;
        #pragma unroll
        for (int it = 0; it < 2; it++) {
            int lin = tid + it * 256;
            int r = lin >> 2;          // row (position or output channel)
            int j = lin & 3;           // 16B chunk within the 64B k-slice
            uint32_t d = st + r * (KST * 2) + j * 16;
            size_t ai = (size_t)(pblock + r) * CCH + kc + j * 8;
            size_t bi = (size_t)(oblock + r) * CCH + kc + j * 8;
            CP16(d + AH_OFF, &g_Ahi[ai]);
            CP16(d + AL_OFF, &g_Alo[ai]);
            CP16(d + BH_OFF, &g_Whi[bi]);
            CP16(d + BL_OFF, &g_Wlo[bi]);
        }
        CPCOMMIT();
    };

    float acc[2][8][4];
    #pragma unroll
    for (int mt = 0; mt < 2; mt++)
        #pragma unroll
        for (int nt = 0; nt < 8; nt++)
            #pragma unroll
            for (int r = 0; r < 4; r++) acc[mt][nt][r] = 0.0f;

    load_stage(0, 0);

    for (int ch = 0; ch < 16; ch++) {
        if (ch < 15) { load_stage((ch + 1) * 32, (ch + 1) & 1); CPWAIT(1); }
        else         { CPWAIT(0); }
        __syncthreads();

        const char* st = dsm + (ch & 1) * STAGE_BYTES;
        const __nv_bfloat16* Ah = (const __nv_bfloat16*)(st + AH_OFF);
        const __nv_bfloat16* Al = (const __nv_bfloat16*)(st + AL_OFF);
        const __nv_bfloat16* Bh = (const __nv_bfloat16*)(st + BH_OFF);
        const __nv_bfloat16* Bl = (const __nv_bfloat16*)(st + BL_OFF);

        #pragma unroll
        for (int kk = 0; kk < 32; kk += 16) {
            uint32_t ah[2][4], al[2][4];
            #pragma unroll
            for (int mt = 0; mt < 2; mt++) {
                int base = (wm * 32 + mt * 16 + g8) * KST + kk + tig2;
                ah[mt][0] = *(const uint32_t*)&Ah[base];
                ah[mt][1] = *(const uint32_t*)&Ah[base + 8 * KST];
                ah[mt][2] = *(const uint32_t*)&Ah[base + 8];
                ah[mt][3] = *(const uint32_t*)&Ah[base + 8 * KST + 8];
                al[mt][0] = *(const uint32_t*)&Al[base];
                al[mt][1] = *(const uint32_t*)&Al[base + 8 * KST];
                al[mt][2] = *(const uint32_t*)&Al[base + 8];
                al[mt][3] = *(const uint32_t*)&Al[base + 8 * KST + 8];
            }
            uint32_t bh[8][2], bl[8][2];
            #pragma unroll
            for (int nt = 0; nt < 8; nt++) {
                int nb = (wn * 64 + nt * 8 + g8) * KST + kk + tig2;
                bh[nt][0] = *(const uint32_t*)&Bh[nb];
                bh[nt][1] = *(const uint32_t*)&Bh[nb + 8];
                bl[nt][0] = *(const uint32_t*)&Bl[nb];
                bl[nt][1] = *(const uint32_t*)&Bl[nb + 8];
            }
            // term-major: 16 independent accs per term -> RAW distance 16
            #pragma unroll
            for (int nt = 0; nt < 8; nt++)
                #pragma unroll
                for (int mt = 0; mt < 2; mt++)
                    MMA_BF16(acc[mt][nt], ah[mt], bh[nt]);
            #pragma unroll
            for (int nt = 0; nt < 8; nt++)
                #pragma unroll
                for (int mt = 0; mt < 2; mt++)
                    MMA_BF16(acc[mt][nt], ah[mt], bl[nt]);
            #pragma unroll
            for (int nt = 0; nt < 8; nt++)
                #pragma unroll
                for (int mt = 0; mt < 2; mt++)
                    MMA_BF16(acc[mt][nt], al[mt], bh[nt]);
        }
        __syncthreads();
    }

    // Epilogue: BN + ReLU (layout verified in Round 2).
    #pragma unroll
    for (int mt = 0; mt < 2; mt++) {
        int p0 = pblock + wm * 32 + mt * 16 + g8;
        int p1 = p0 + 8;
        int b0 = p0 / HW, hw0 = p0 - b0 * HW;
        int b1 = p1 / HW, hw1 = p1 - b1 * HW;
        #pragma unroll
        for (int nt = 0; nt < 8; nt++) {
            int oo  = wn * 64 + nt * 8 + tig2;
            float sc0 = ssc[oo],     sh0 = ssh[oo];
            float sc1 = ssc[oo + 1], sh1 = ssh[oo + 1];
            int o0 = oblock + oo;
            float* q00 = out + ((size_t)(b0 * CCH + o0)) * HW + hw0;
            float* q01 = out + ((size_t)(b0 * CCH + o0 + 1)) * HW + hw0;
            float* q10 = out + ((size_t)(b1 * CCH + o0)) * HW + hw1;
            float* q11 = out + ((size_t)(b1 * CCH + o0 + 1)) * HW + hw1;
            *q00 = fmaxf(fmaf(acc[mt][nt][0], sc0, sh0), 0.0f);
            *q01 = fmaxf(fmaf(acc[mt][nt][1], sc1, sh1), 0.0f);
            *q10 = fmaxf(fmaf(acc[mt][nt][2], sc0, sh0), 0.0f);
            *q11 = fmaxf(fmaf(acc[mt][nt][3], sc1, sh1), 0.0f);
        }
    }
}

extern "C" void kernel_launch(void* const* d_in, const int* in_sizes, int n_in,
                              void* d_out, int out_size)
{
    const float* x     = (const float*)d_in[0];
    const float* Wm    = (const float*)d_in[1];
    const float* gamma = (const float*)d_in[2];
    const float* beta  = (const float*)d_in[3];
    const float* rmean = (const float*)d_in[4];
    const float* rvar  = (const float*)d_in[5];
    float* out = (float*)d_out;

    cudaFuncSetAttribute(shiftconv_gemm,
                         cudaFuncAttributeMaxDynamicSharedMemorySize, SMEM_TOTAL);

    split_w_kernel<<<CCH * CCH / 256, 256>>>(Wm);
    dim3 pgrid(50176 / 64, CCH / 64);
    shift_split_x<<<pgrid, 256>>>(x);
    dim3 grid(392, 4);
    shiftconv_gemm<<<grid, 256, SMEM_TOTAL>>>(gamma, beta, rmean, rvar, out);
}

// round 5
// speedup vs baseline: 5.1251x; 1.3892x over previous
#include <cuda_runtime.h>
#include <cuda_fp16.h>
#include <cstdint>

// ShiftConv: shift -> 1x1 conv (GEMM M=50176,N=512,K=512) -> BN -> ReLU.
// Round 5: fp16 2-term split. A = fp16(shifted x) single term; W split into
// fp16 hi+lo. y = Ah*Wh + Ah*Wl (= Ah*W exactly in fp32 accum); error is only
// fp16 rounding of A (~1e-4 rel). 33% fewer MMAs than the 3-term bf16 kernel,
// half the A prepass/stream traffic.

#define HDIM 28
#define HW   784
#define CCH  512
#define EPSV 1e-5f

#define MMA_F16(C, A, B) \
  asm volatile("mma.sync.aligned.m16n8k16.row.col.f32.f16.f16.f32 " \
    "{%0,%1,%2,%3}, {%4,%5,%6,%7}, {%8,%9}, {%0,%1,%2,%3};" \
    : "+f"((C)[0]), "+f"((C)[1]), "+f"((C)[2]), "+f"((C)[3]) \
    : "r"((A)[0]), "r"((A)[1]), "r"((A)[2]), "r"((A)[3]), \
      "r"((B)[0]), "r"((B)[1]))

#define CP16(dst, src) \
  asm volatile("cp.async.ca.shared.global [%0], [%1], 16;" :: "r"(dst), "l"(src))
#define CPCOMMIT() asm volatile("cp.async.commit_group;" ::: "memory")
#define CPWAIT(n)  asm volatile("cp.async.wait_group %0;" :: "n"(n) : "memory")

// smem row stride: 32 real + 8 pad fp16 (80B, 16B aligned)
#define KST 40
#define MAT_BYTES (128 * KST * 2)          // 10240
#define AH_OFF 0
#define BH_OFF (1 * MAT_BYTES)
#define BL_OFF (2 * MAT_BYTES)
#define STAGE_BYTES (3 * MAT_BYTES)        // 30720
#define SMEM_TOTAL (2 * STAGE_BYTES)       // 61440

__device__ __half g_Whi[CCH * CCH];
__device__ __half g_Wlo[CCH * CCH];
__device__ __half g_Ah[(size_t)50176 * CCH];   // shifted x, fp16, [p][c]

__device__ __forceinline__ uint32_t smem_u32(const void* p) {
    uint32_t a;
    asm("{ .reg .u64 t; cvta.to.shared.u64 t, %1; cvt.u32.u64 %0, t; }"
        : "=r"(a) : "l"(p));
    return a;
}

__global__ void split_w_kernel(const float* __restrict__ Wm) {
    int i = blockIdx.x * 256 + threadIdx.x;
    float v = Wm[i];
    __half h = __float2half_rn(v);
    g_Whi[i] = h;
    g_Wlo[i] = __float2half_rn(v - __half2float(h));
}

// Gather (shift) + transpose + fp16 convert: x[B,C,H,W] -> Ah[p][c].
__global__ __launch_bounds__(256)
void shift_split_x(const float* __restrict__ x) {
    __shared__ float tile[64][65];
    __shared__ int soff[64];
    const int tid = threadIdx.x;
    const int p0 = blockIdx.x * 64;
    const int c0 = blockIdx.y * 64;
    const int g  = c0 >> 7;

    if (tid < 64) {
        int pg = p0 + tid;
        int b  = pg / HW;
        int hw = pg - b * HW;
        int h  = hw / HDIM;
        int w  = hw - h * HDIM;
        int hs = h, ws = w;
        if      (g == 0) hs = (h + 1) % HDIM;
        else if (g == 1) hs = (h + HDIM - 1) % HDIM;
        else if (g == 2) ws = (w + 1) % HDIM;
        else             ws = (w + HDIM - 1) % HDIM;
        soff[tid] = b * (CCH * HW) + hs * HDIM + ws;
    }
    __syncthreads();
    #pragma unroll
    for (int it = 0; it < 16; it++) {       // read coalesced over p
        int lin = tid + it * 256;
        int c = lin >> 6, p = lin & 63;
        tile[c][p] = x[(size_t)(c0 + c) * HW + soff[p]];
    }
    __syncthreads();
    #pragma unroll
    for (int it = 0; it < 16; it++) {       // write coalesced over c
        int lin = tid + it * 256;
        int p = lin >> 6, c = lin & 63;
        g_Ah[(size_t)(p0 + p) * CCH + c0 + c] = __float2half_rn(tile[c][p]);
    }
}

__global__ __launch_bounds__(256, 2)
void shiftconv_gemm(const float* __restrict__ gamma,
                    const float* __restrict__ beta,
                    const float* __restrict__ rmean,
                    const float* __restrict__ rvar,
                    float* __restrict__ out)
{
    extern __shared__ char dsm[];
    __shared__ float ssc[128], ssh[128];

    const int tid  = threadIdx.x;
    const int lane = tid & 31;
    const int wid  = tid >> 5;
    const int wm   = wid & 3;
    const int wn   = wid >> 2;
    const int g8   = lane >> 2;
    const int tig2 = (lane & 3) * 2;

    const int pblock = blockIdx.x * 128;
    const int oblock = blockIdx.y * 128;

    if (tid < 128) {
        int o = oblock + tid;
        float sc = gamma[o] * rsqrtf(rvar[o] + EPSV);
        ssc[tid] = sc;
        ssh[tid] = beta[o] - rmean[o] * sc;
    }

    const uint32_t sdyn = smem_u32(dsm);

    // stage loader: 6 x 16B cp.async per thread (Ah/Bh/Bl, 64B per row)
    auto load_stage = [&](int kc, int buf) {
        uint32_t st = sdyn + buf * STAGE_BYTES;
        #pragma unroll
        for (int it = 0; it < 2; it++) {
            int lin = tid + it * 256;
            int r = lin >> 2;          // row (position or output channel)
            int j = lin & 3;           // 16B chunk within the 64B k-slice
            uint32_t d = st + r * (KST * 2) + j * 16;
            size_t ai = (size_t)(pblock + r) * CCH + kc + j * 8;
            size_t bi = (size_t)(oblock + r) * CCH + kc + j * 8;
            CP16(d + AH_OFF, &g_Ah[ai]);
            CP16(d + BH_OFF, &g_Whi[bi]);
            CP16(d + BL_OFF, &g_Wlo[bi]);
        }
        CPCOMMIT();
    };

    float acc[2][8][4];
    #pragma unroll
    for (int mt = 0; mt < 2; mt++)
        #pragma unroll
        for (int nt = 0; nt < 8; nt++)
            #pragma unroll
            for (int r = 0; r < 4; r++) acc[mt][nt][r] = 0.0f;

    load_stage(0, 0);

    for (int ch = 0; ch < 16; ch++) {
        if (ch < 15) { load_stage((ch + 1) * 32, (ch + 1) & 1); CPWAIT(1); }
        else         { CPWAIT(0); }
        __syncthreads();

        const char* st = dsm + (ch & 1) * STAGE_BYTES;
        const __half* Ah = (const __half*)(st + AH_OFF);
        const __half* Bh = (const __half*)(st + BH_OFF);
        const __half* Bl = (const __half*)(st + BL_OFF);

        #pragma unroll
        for (int kk = 0; kk < 32; kk += 16) {
            uint32_t ah[2][4];
            #pragma unroll
            for (int mt = 0; mt < 2; mt++) {
                int base = (wm * 32 + mt * 16 + g8) * KST + kk + tig2;
                ah[mt][0] = *(const uint32_t*)&Ah[base];
                ah[mt][1] = *(const uint32_t*)&Ah[base + 8 * KST];
                ah[mt][2] = *(const uint32_t*)&Ah[base + 8];
                ah[mt][3] = *(const uint32_t*)&Ah[base + 8 * KST + 8];
            }
            uint32_t bh[8][2], bl[8][2];
            #pragma unroll
            for (int nt = 0; nt < 8; nt++) {
                int nb = (wn * 64 + nt * 8 + g8) * KST + kk + tig2;
                bh[nt][0] = *(const uint32_t*)&Bh[nb];
                bh[nt][1] = *(const uint32_t*)&Bh[nb + 8];
                bl[nt][0] = *(const uint32_t*)&Bl[nb];
                bl[nt][1] = *(const uint32_t*)&Bl[nb + 8];
            }
            // term-major: 16 independent accumulators per term
            #pragma unroll
            for (int nt = 0; nt < 8; nt++)
                #pragma unroll
                for (int mt = 0; mt < 2; mt++)
                    MMA_F16(acc[mt][nt], ah[mt], bh[nt]);
            #pragma unroll
            for (int nt = 0; nt < 8; nt++)
                #pragma unroll
                for (int mt = 0; mt < 2; mt++)
                    MMA_F16(acc[mt][nt], ah[mt], bl[nt]);
        }
        __syncthreads();
    }

    // Epilogue: BN + ReLU.
    #pragma unroll
    for (int mt = 0; mt < 2; mt++) {
        int p0 = pblock + wm * 32 + mt * 16 + g8;
        int p1 = p0 + 8;
        int b0 = p0 / HW, hw0 = p0 - b0 * HW;
        int b1 = p1 / HW, hw1 = p1 - b1 * HW;
        #pragma unroll
        for (int nt = 0; nt < 8; nt++) {
            int oo  = wn * 64 + nt * 8 + tig2;
            float sc0 = ssc[oo],     sh0 = ssh[oo];
            float sc1 = ssc[oo + 1], sh1 = ssh[oo + 1];
            int o0 = oblock + oo;
            float* q00 = out + ((size_t)(b0 * CCH + o0)) * HW + hw0;
            float* q01 = out + ((size_t)(b0 * CCH + o0 + 1)) * HW + hw0;
            float* q10 = out + ((size_t)(b1 * CCH + o0)) * HW + hw1;
            float* q11 = out + ((size_t)(b1 * CCH + o0 + 1)) * HW + hw1;
            *q00 = fmaxf(fmaf(acc[mt][nt][0], sc0, sh0), 0.0f);
            *q01 = fmaxf(fmaf(acc[mt][nt][1], sc1, sh1), 0.0f);
            *q10 = fmaxf(fmaf(acc[mt][nt][2], sc0, sh0), 0.0f);
            *q11 = fmaxf(fmaf(acc[mt][nt][3], sc1, sh1), 0.0f);
        }
    }
}

extern "C" void kernel_launch(void* const* d_in, const int* in_sizes, int n_in,
                              void* d_out, int out_size)
{
    const float* x     = (const float*)d_in[0];
    const float* Wm    = (const float*)d_in[1];
    const float* gamma = (const float*)d_in[2];
    const float* beta  = (const float*)d_in[3];
    const float* rmean = (const float*)d_in[4];
    const float* rvar  = (const float*)d_in[5];
    float* out = (float*)d_out;

    cudaFuncSetAttribute(shiftconv_gemm,
                         cudaFuncAttributeMaxDynamicSharedMemorySize, SMEM_TOTAL);

    split_w_kernel<<<CCH * CCH / 256, 256>>>(Wm);
    dim3 pgrid(50176 / 64, CCH / 64);
    shift_split_x<<<pgrid, 256>>>(x);
    dim3 grid(392, 4);
    shiftconv_gemm<<<grid, 256, SMEM_TOTAL>>>(gamma, beta, rmean, rvar, out);
}

// round 6
// speedup vs baseline: 8.1858x; 1.5972x over previous
#include <cuda_runtime.h>
#include <cuda_fp16.h>
#include <cstdint>

// ShiftConv: shift -> 1x1 conv (GEMM M=50176,N=512,K=512) -> BN -> ReLU.
// Round 6: single-term fp16 GEMM (A and W both rounded to fp16, fp32 accum).
// Measured 2-term error (A-rounding only) was 2.06e-4; adding W rounding gives
// ~sqrt(2)x => ~2.9e-4, still 3.4x under the 1e-3 gate. Halves MMA work vs R5.
// K-chunk widened to 64 (8 chunks, half the barriers), double-buffered.

#define HDIM 28
#define HW   784
#define CCH  512
#define EPSV 1e-5f

#define MMA_F16(C, A, B) \
  asm volatile("mma.sync.aligned.m16n8k16.row.col.f32.f16.f16.f32 " \
    "{%0,%1,%2,%3}, {%4,%5,%6,%7}, {%8,%9}, {%0,%1,%2,%3};" \
    : "+f"((C)[0]), "+f"((C)[1]), "+f"((C)[2]), "+f"((C)[3]) \
    : "r"((A)[0]), "r"((A)[1]), "r"((A)[2]), "r"((A)[3]), \
      "r"((B)[0]), "r"((B)[1]))

#define CP16(dst, src) \
  asm volatile("cp.async.ca.shared.global [%0], [%1], 16;" :: "r"(dst), "l"(src))
#define CPCOMMIT() asm volatile("cp.async.commit_group;" ::: "memory")
#define CPWAIT(n)  asm volatile("cp.async.wait_group %0;" :: "n"(n) : "memory")

// K-chunk 64; smem row stride 64 real + 8 pad fp16 (144B, 16B aligned)
#define KC  64
#define KST 72
#define MAT_BYTES (128 * KST * 2)          // 18432
#define A_OFF 0
#define B_OFF MAT_BYTES
#define STAGE_BYTES (2 * MAT_BYTES)        // 36864
#define SMEM_TOTAL (2 * STAGE_BYTES)       // 73728

__device__ __half g_Wh[CCH * CCH];
__device__ __half g_Ah[(size_t)50176 * CCH];   // shifted x, fp16, [p][c]

__device__ __forceinline__ uint32_t smem_u32(const void* p) {
    uint32_t a;
    asm("{ .reg .u64 t; cvta.to.shared.u64 t, %1; cvt.u32.u64 %0, t; }"
        : "=r"(a) : "l"(p));
    return a;
}

__global__ void conv_w_kernel(const float* __restrict__ Wm) {
    int i = blockIdx.x * 256 + threadIdx.x;
    g_Wh[i] = __float2half_rn(Wm[i]);
}

// Gather (shift) + transpose + fp16 convert: x[B,C,H,W] -> Ah[p][c].
__global__ __launch_bounds__(256)
void shift_split_x(const float* __restrict__ x) {
    __shared__ float tile[64][65];
    __shared__ int soff[64];
    const int tid = threadIdx.x;
    const int p0 = blockIdx.x * 64;
    const int c0 = blockIdx.y * 64;
    const int g  = c0 >> 7;

    if (tid < 64) {
        int pg = p0 + tid;
        int b  = pg / HW;
        int hw = pg - b * HW;
        int h  = hw / HDIM;
        int w  = hw - h * HDIM;
        int hs = h, ws = w;
        if      (g == 0) hs = (h + 1) % HDIM;
        else if (g == 1) hs = (h + HDIM - 1) % HDIM;
        else if (g == 2) ws = (w + 1) % HDIM;
        else             ws = (w + HDIM - 1) % HDIM;
        soff[tid] = b * (CCH * HW) + hs * HDIM + ws;
    }
    __syncthreads();
    #pragma unroll
    for (int it = 0; it < 16; it++) {       // read coalesced over p
        int lin = tid + it * 256;
        int c = lin >> 6, p = lin & 63;
        tile[c][p] = x[(size_t)(c0 + c) * HW + soff[p]];
    }
    __syncthreads();
    #pragma unroll
    for (int it = 0; it < 16; it++) {       // write coalesced over c
        int lin = tid + it * 256;
        int p = lin >> 6, c = lin & 63;
        g_Ah[(size_t)(p0 + p) * CCH + c0 + c] = __float2half_rn(tile[c][p]);
    }
}

__global__ __launch_bounds__(256, 2)
void shiftconv_gemm(const float* __restrict__ gamma,
                    const float* __restrict__ beta,
                    const float* __restrict__ rmean,
                    const float* __restrict__ rvar,
                    float* __restrict__ out)
{
    extern __shared__ char dsm[];
    __shared__ float ssc[128], ssh[128];

    const int tid  = threadIdx.x;
    const int lane = tid & 31;
    const int wid  = tid >> 5;
    const int wm   = wid & 3;
    const int wn   = wid >> 2;
    const int g8   = lane >> 2;
    const int tig2 = (lane & 3) * 2;

    const int pblock = blockIdx.x * 128;
    const int oblock = blockIdx.y * 128;

    if (tid < 128) {
        int o = oblock + tid;
        float sc = gamma[o] * rsqrtf(rvar[o] + EPSV);
        ssc[tid] = sc;
        ssh[tid] = beta[o] - rmean[o] * sc;
    }

    const uint32_t sdyn = smem_u32(dsm);

    // stage loader: 128 rows x 128B (A and B), 8 x 16B cp.async per thread
    auto load_stage = [&](int kc, int buf) {
        uint32_t st = sdyn + buf * STAGE_BYTES;
        #pragma unroll
        for (int it = 0; it < 4; it++) {
            int lin = tid + it * 256;
            int r = lin >> 3;          // row (position or output channel)
            int j = lin & 7;           // 16B chunk within the 128B k-slice
            uint32_t d = st + r * (KST * 2) + j * 16;
            CP16(d + A_OFF, &g_Ah[(size_t)(pblock + r) * CCH + kc + j * 8]);
            CP16(d + B_OFF, &g_Wh[(size_t)(oblock + r) * CCH + kc + j * 8]);
        }
        CPCOMMIT();
    };

    float acc[2][8][4];
    #pragma unroll
    for (int mt = 0; mt < 2; mt++)
        #pragma unroll
        for (int nt = 0; nt < 8; nt++)
            #pragma unroll
            for (int r = 0; r < 4; r++) acc[mt][nt][r] = 0.0f;

    load_stage(0, 0);

    for (int ch = 0; ch < 8; ch++) {
        if (ch < 7) { load_stage((ch + 1) * KC, (ch + 1) & 1); CPWAIT(1); }
        else        { CPWAIT(0); }
        __syncthreads();

        const char* st = dsm + (ch & 1) * STAGE_BYTES;
        const __half* Ah = (const __half*)(st + A_OFF);
        const __half* Bh = (const __half*)(st + B_OFF);

        #pragma unroll
        for (int kk = 0; kk < KC; kk += 16) {
            uint32_t ah[2][4];
            #pragma unroll
            for (int mt = 0; mt < 2; mt++) {
                int base = (wm * 32 + mt * 16 + g8) * KST + kk + tig2;
                ah[mt][0] = *(const uint32_t*)&Ah[base];
                ah[mt][1] = *(const uint32_t*)&Ah[base + 8 * KST];
                ah[mt][2] = *(const uint32_t*)&Ah[base + 8];
                ah[mt][3] = *(const uint32_t*)&Ah[base + 8 * KST + 8];
            }
            uint32_t bh[8][2];
            #pragma unroll
            for (int nt = 0; nt < 8; nt++) {
                int nb = (wn * 64 + nt * 8 + g8) * KST + kk + tig2;
                bh[nt][0] = *(const uint32_t*)&Bh[nb];
                bh[nt][1] = *(const uint32_t*)&Bh[nb + 8];
            }
            #pragma unroll
            for (int nt = 0; nt < 8; nt++)
                #pragma unroll
                for (int mt = 0; mt < 2; mt++)
                    MMA_F16(acc[mt][nt], ah[mt], bh[nt]);
        }
        __syncthreads();
    }

    // Epilogue: BN + ReLU.
    #pragma unroll
    for (int mt = 0; mt < 2; mt++) {
        int p0 = pblock + wm * 32 + mt * 16 + g8;
        int p1 = p0 + 8;
        int b0 = p0 / HW, hw0 = p0 - b0 * HW;
        int b1 = p1 / HW, hw1 = p1 - b1 * HW;
        #pragma unroll
        for (int nt = 0; nt < 8; nt++) {
            int oo  = wn * 64 + nt * 8 + tig2;
            float sc0 = ssc[oo],     sh0 = ssh[oo];
            float sc1 = ssc[oo + 1], sh1 = ssh[oo + 1];
            int o0 = oblock + oo;
            float* q00 = out + ((size_t)(b0 * CCH + o0)) * HW + hw0;
            float* q01 = out + ((size_t)(b0 * CCH + o0 + 1)) * HW + hw0;
            float* q10 = out + ((size_t)(b1 * CCH + o0)) * HW + hw1;
            float* q11 = out + ((size_t)(b1 * CCH + o0 + 1)) * HW + hw1;
            *q00 = fmaxf(fmaf(acc[mt][nt][0], sc0, sh0), 0.0f);
            *q01 = fmaxf(fmaf(acc[mt][nt][1], sc1, sh1), 0.0f);
            *q10 = fmaxf(fmaf(acc[mt][nt][2], sc0, sh0), 0.0f);
            *q11 = fmaxf(fmaf(acc[mt][nt][3], sc1, sh1), 0.0f);
        }
    }
}

extern "C" void kernel_launch(void* const* d_in, const int* in_sizes, int n_in,
                              void* d_out, int out_size)
{
    const float* x     = (const float*)d_in[0];
    const float* Wm    = (const float*)d_in[1];
    const float* gamma = (const float*)d_in[2];
    const float* beta  = (const float*)d_in[3];
    const float* rmean = (const float*)d_in[4];
    const float* rvar  = (const float*)d_in[5];
    float* out = (float*)d_out;

    cudaFuncSetAttribute(shiftconv_gemm,
                         cudaFuncAttributeMaxDynamicSharedMemorySize, SMEM_TOTAL);

    conv_w_kernel<<<CCH * CCH / 256, 256>>>(Wm);
    dim3 pgrid(50176 / 64, CCH / 64);
    shift_split_x<<<pgrid, 256>>>(x);
    dim3 grid(392, 4);
    shiftconv_gemm<<<grid, 256, SMEM_TOTAL>>>(gamma, beta, rmean, rvar, out);
}

// round 7
// speedup vs baseline: 8.6249x; 1.0537x over previous
#include <cuda_runtime.h>
#include <cuda_fp16.h>
#include <cstdint>

// ShiftConv: shift -> 1x1 conv (GEMM M=50176,N=512,K=512) -> BN -> ReLU.
// Round 7: R6 single-term fp16 GEMM + ldmatrix fragment loads.
// 24 scalar LDS per k16-step -> 6 ldmatrix.x4 (4x fewer smem instructions);
// KST=72 halves (144B row stride) keeps the 8-row LDSM phases conflict-free.

#define HDIM 28
#define HW   784
#define CCH  512
#define EPSV 1e-5f

#define MMA_F16(C, A, B) \
  asm volatile("mma.sync.aligned.m16n8k16.row.col.f32.f16.f16.f32 " \
    "{%0,%1,%2,%3}, {%4,%5,%6,%7}, {%8,%9}, {%0,%1,%2,%3};" \
    : "+f"((C)[0]), "+f"((C)[1]), "+f"((C)[2]), "+f"((C)[3]) \
    : "r"((A)[0]), "r"((A)[1]), "r"((A)[2]), "r"((A)[3]), \
      "r"((B)[0]), "r"((B)[1]))

#define LDSM4(R0, R1, R2, R3, addr) \
  asm volatile("ldmatrix.sync.aligned.m8n8.x4.shared.b16 {%0,%1,%2,%3}, [%4];" \
    : "=r"(R0), "=r"(R1), "=r"(R2), "=r"(R3) : "r"(addr))

#define CP16(dst, src) \
  asm volatile("cp.async.ca.shared.global [%0], [%1], 16;" :: "r"(dst), "l"(src))
#define CPCOMMIT() asm volatile("cp.async.commit_group;" ::: "memory")
#define CPWAIT(n)  asm volatile("cp.async.wait_group %0;" :: "n"(n) : "memory")

// K-chunk 64; smem row stride 64 real + 8 pad fp16 (144B, 16B aligned)
#define KC  64
#define KST 72
#define MAT_BYTES (128 * KST * 2)          // 18432
#define A_OFF 0
#define B_OFF MAT_BYTES
#define STAGE_BYTES (2 * MAT_BYTES)        // 36864
#define SMEM_TOTAL (2 * STAGE_BYTES)       // 73728

__device__ __half g_Wh[CCH * CCH];
__device__ __half g_Ah[(size_t)50176 * CCH];   // shifted x, fp16, [p][c]

__device__ __forceinline__ uint32_t smem_u32(const void* p) {
    uint32_t a;
    asm("{ .reg .u64 t; cvta.to.shared.u64 t, %1; cvt.u32.u64 %0, t; }"
        : "=r"(a) : "l"(p));
    return a;
}

__global__ void conv_w_kernel(const float* __restrict__ Wm) {
    int i = blockIdx.x * 256 + threadIdx.x;
    g_Wh[i] = __float2half_rn(Wm[i]);
}

// Gather (shift) + transpose + fp16 convert: x[B,C,H,W] -> Ah[p][c].
__global__ __launch_bounds__(256)
void shift_split_x(const float* __restrict__ x) {
    __shared__ float tile[64][65];
    __shared__ int soff[64];
    const int tid = threadIdx.x;
    const int p0 = blockIdx.x * 64;
    const int c0 = blockIdx.y * 64;
    const int g  = c0 >> 7;

    if (tid < 64) {
        int pg = p0 + tid;
        int b  = pg / HW;
        int hw = pg - b * HW;
        int h  = hw / HDIM;
        int w  = hw - h * HDIM;
        int hs = h, ws = w;
        if      (g == 0) hs = (h + 1) % HDIM;
        else if (g == 1) hs = (h + HDIM - 1) % HDIM;
        else if (g == 2) ws = (w + 1) % HDIM;
        else             ws = (w + HDIM - 1) % HDIM;
        soff[tid] = b * (CCH * HW) + hs * HDIM + ws;
    }
    __syncthreads();
    #pragma unroll
    for (int it = 0; it < 16; it++) {       // read coalesced over p
        int lin = tid + it * 256;
        int c = lin >> 6, p = lin & 63;
        tile[c][p] = x[(size_t)(c0 + c) * HW + soff[p]];
    }
    __syncthreads();
    #pragma unroll
    for (int it = 0; it < 16; it++) {       // write coalesced over c
        int lin = tid + it * 256;
        int p = lin >> 6, c = lin & 63;
        g_Ah[(size_t)(p0 + p) * CCH + c0 + c] = __float2half_rn(tile[c][p]);
    }
}

__global__ __launch_bounds__(256, 2)
void shiftconv_gemm(const float* __restrict__ gamma,
                    const float* __restrict__ beta,
                    const float* __restrict__ rmean,
                    const float* __restrict__ rvar,
                    float* __restrict__ out)
{
    extern __shared__ char dsm[];
    __shared__ float ssc[128], ssh[128];

    const int tid  = threadIdx.x;
    const int lane = tid & 31;
    const int wid  = tid >> 5;
    const int wm   = wid & 3;
    const int wn   = wid >> 2;
    const int g8   = lane >> 2;
    const int tig2 = (lane & 3) * 2;
    const int q    = lane >> 3;        // ldmatrix quad (which 8x8 matrix)
    const int r8   = lane & 7;         // ldmatrix row within matrix

    const int pblock = blockIdx.x * 128;
    const int oblock = blockIdx.y * 128;

    if (tid < 128) {
        int o = oblock + tid;
        float sc = gamma[o] * rsqrtf(rvar[o] + EPSV);
        ssc[tid] = sc;
        ssh[tid] = beta[o] - rmean[o] * sc;
    }

    const uint32_t sdyn = smem_u32(dsm);

    // ldmatrix per-thread base byte offsets (kk and buf added in-loop).
    // A x4 for m-tile mt: matrices {m0 k0, m0+8 k0, m0 k8, m0+8 k8}
    uint32_t aoff[2];
    #pragma unroll
    for (int mt = 0; mt < 2; mt++)
        aoff[mt] = (uint32_t)(((wm * 32 + mt * 16 + (q & 1) * 8 + r8) * KST
                               + (q >> 1) * 8) * 2) + A_OFF;
    // B x4 for n-tile pair np: {n0 k0, n0 k8, n0+8 k0, n0+8 k8}
    //  -> R0/R1 = b-frag of ntile 2np, R2/R3 = ntile 2np+1
    uint32_t boff[4];
    #pragma unroll
    for (int np = 0; np < 4; np++)
        boff[np] = (uint32_t)(((wn * 64 + np * 16 + (q >> 1) * 8 + r8) * KST
                               + (q & 1) * 8) * 2) + B_OFF;

    // stage loader: 128 rows x 128B (A and B), 8 x 16B cp.async per thread
    auto load_stage = [&](int kc, int buf) {
        uint32_t st = sdyn + buf * STAGE_BYTES;
        #pragma unroll
        for (int it = 0; it < 4; it++) {
            int lin = tid + it * 256;
            int r = lin >> 3;          // row (position or output channel)
            int j = lin & 7;           // 16B chunk within the 128B k-slice
            uint32_t d = st + r * (KST * 2) + j * 16;
            CP16(d + A_OFF, &g_Ah[(size_t)(pblock + r) * CCH + kc + j * 8]);
            CP16(d + B_OFF, &g_Wh[(size_t)(oblock + r) * CCH + kc + j * 8]);
        }
        CPCOMMIT();
    };

    float acc[2][8][4];
    #pragma unroll
    for (int mt = 0; mt < 2; mt++)
        #pragma unroll
        for (int nt = 0; nt < 8; nt++)
            #pragma unroll
            for (int rr = 0; rr < 4; rr++) acc[mt][nt][rr] = 0.0f;

    load_stage(0, 0);

    for (int ch = 0; ch < 8; ch++) {
        if (ch < 7) { load_stage((ch + 1) * KC, (ch + 1) & 1); CPWAIT(1); }
        else        { CPWAIT(0); }
        __syncthreads();

        const uint32_t st = sdyn + (ch & 1) * STAGE_BYTES;

        #pragma unroll
        for (int kk = 0; kk < KC; kk += 16) {
            const uint32_t kb = st + kk * 2;
            uint32_t ah[2][4];
            #pragma unroll
            for (int mt = 0; mt < 2; mt++)
                LDSM4(ah[mt][0], ah[mt][1], ah[mt][2], ah[mt][3], kb + aoff[mt]);
            uint32_t bh[8][2];
            #pragma unroll
            for (int np = 0; np < 4; np++)
                LDSM4(bh[2 * np][0], bh[2 * np][1],
                      bh[2 * np + 1][0], bh[2 * np + 1][1], kb + boff[np]);
            #pragma unroll
            for (int nt = 0; nt < 8; nt++)
                #pragma unroll
                for (int mt = 0; mt < 2; mt++)
                    MMA_F16(acc[mt][nt], ah[mt], bh[nt]);
        }
        __syncthreads();
    }

    // Epilogue: BN + ReLU.
    #pragma unroll
    for (int mt = 0; mt < 2; mt++) {
        int p0 = pblock + wm * 32 + mt * 16 + g8;
        int p1 = p0 + 8;
        int b0 = p0 / HW, hw0 = p0 - b0 * HW;
        int b1 = p1 / HW, hw1 = p1 - b1 * HW;
        #pragma unroll
        for (int nt = 0; nt < 8; nt++) {
            int oo  = wn * 64 + nt * 8 + tig2;
            float sc0 = ssc[oo],     sh0 = ssh[oo];
            float sc1 = ssc[oo + 1], sh1 = ssh[oo + 1];
            int o0 = oblock + oo;
            float* q00 = out + ((size_t)(b0 * CCH + o0)) * HW + hw0;
            float* q01 = out + ((size_t)(b0 * CCH + o0 + 1)) * HW + hw0;
            float* q10 = out + ((size_t)(b1 * CCH + o0)) * HW + hw1;
            float* q11 = out + ((size_t)(b1 * CCH + o0 + 1)) * HW + hw1;
            *q00 = fmaxf(fmaf(acc[mt][nt][0], sc0, sh0), 0.0f);
            *q01 = fmaxf(fmaf(acc[mt][nt][1], sc1, sh1), 0.0f);
            *q10 = fmaxf(fmaf(acc[mt][nt][2], sc0, sh0), 0.0f);
            *q11 = fmaxf(fmaf(acc[mt][nt][3], sc1, sh1), 0.0f);
        }
    }
}

extern "C" void kernel_launch(void* const* d_in, const int* in_sizes, int n_in,
                              void* d_out, int out_size)
{
    const float* x     = (const float*)d_in[0];
    const float* Wm    = (const float*)d_in[1];
    const float* gamma = (const float*)d_in[2];
    const float* beta  = (const float*)d_in[3];
    const float* rmean = (const float*)d_in[4];
    const float* rvar  = (const float*)d_in[5];
    float* out = (float*)d_out;

    cudaFuncSetAttribute(shiftconv_gemm,
                         cudaFuncAttributeMaxDynamicSharedMemorySize, SMEM_TOTAL);

    conv_w_kernel<<<CCH * CCH / 256, 256>>>(Wm);
    dim3 pgrid(50176 / 64, CCH / 64);
    shift_split_x<<<pgrid, 256>>>(x);
    dim3 grid(392, 4);
    shiftconv_gemm<<<grid, 256, SMEM_TOTAL>>>(gamma, beta, rmean, rvar, out);
}